// round 16
// baseline (speedup 1.0000x reference)
#include <cuda_runtime.h>
#include <cuda_bf16.h>
#include <cstdint>
#include <math.h>

#define TTOK 8192
#define DM   1024
#define DFF  4096
#define NE   8
#define BM   128

// smem tile: 128 rows x 32 bf16 (64B data), row stride 80B (20 words ->
// conflict-free ldmatrix). 4 tiles/stage (Ah,Al,Bh,Bl), 4 stages, 1 CTA/SM.
#define TILE_B   10240       // 128 * 80
#define STAGE_B  40960       // 4 * TILE_B
#define NSTAGE   4
#define SMEM_DYN (NSTAGE * STAGE_B)   // 160 KB

// ---------------- device scratch ----------------
__device__ int   g_counts[NE];
__device__ int   g_pair[NE][TTOK];
__device__ float g_wt[NE][TTOK];
__device__ __nv_bfloat16 g_xh[(size_t)TTOK * DM],        g_xl[(size_t)TTOK * DM];
__device__ __nv_bfloat16 g_Wgh[(size_t)NE * DFF * DM],   g_Wgl[(size_t)NE * DFF * DM];
__device__ __nv_bfloat16 g_W1h[(size_t)NE * DFF * DM],   g_W1l[(size_t)NE * DFF * DM];
__device__ __nv_bfloat16 g_W2h[(size_t)NE * DM * DFF],   g_W2l[(size_t)NE * DM * DFF];
__device__ __nv_bfloat16 g_Hh[(size_t)2 * TTOK * DFF],   g_Hl[(size_t)2 * TTOK * DFF];
__device__ float g_Y[(size_t)2 * TTOK * DM];

// ---------------- helpers ----------------
__device__ __forceinline__ uint32_t smem_u32(const void* p) {
    uint32_t a;
    asm("{ .reg .u64 t; cvta.to.shared.u64 t, %1; cvt.u32.u64 %0, t; }" : "=r"(a) : "l"(p));
    return a;
}
__device__ __forceinline__ void ldsm4(uint32_t* r, uint32_t addr) {
    asm volatile("ldmatrix.sync.aligned.m8n8.x4.shared.b16 {%0,%1,%2,%3}, [%4];"
                 : "=r"(r[0]), "=r"(r[1]), "=r"(r[2]), "=r"(r[3]) : "r"(addr));
}
__device__ __forceinline__ void mma16816(float* d, const uint32_t* A, uint32_t b0, uint32_t b1) {
    asm volatile(
        "mma.sync.aligned.m16n8k16.row.col.f32.bf16.bf16.f32 "
        "{%0,%1,%2,%3}, {%4,%5,%6,%7}, {%8,%9}, {%0,%1,%2,%3};"
        : "+f"(d[0]), "+f"(d[1]), "+f"(d[2]), "+f"(d[3])
        : "r"(A[0]), "r"(A[1]), "r"(A[2]), "r"(A[3]), "r"(b0), "r"(b1));
}
#define CP16(dst, src) asm volatile("cp.async.cg.shared.global [%0], [%1], 16;" :: "r"(dst), "l"(src) : "memory")
#define CP_COMMIT()    asm volatile("cp.async.commit_group;" ::: "memory")
#define CP_WAITN(n)    asm volatile("cp.async.wait_group %0;" :: "n"(n) : "memory")

// 3-pass hi/lo compute on one K-chunk (32 bf16), warp tile 32m x 32n.
// Tiles at st+0:Ah, +TILE_B:Al, +2*TILE_B:Bh, +3*TILE_B:Bl.
__device__ __forceinline__ void compute_chunk(uint32_t st, int warp_m, int warp_n,
                                              int lane, float acc[2][4][4]) {
    int lrow = lane & 7;
    int lsel = (lane >> 3) & 1;
    int lk   = lane >> 4;
#pragma unroll
    for (int pass = 0; pass < 3; pass++) {
        uint32_t ab = st + (pass == 2 ? TILE_B : 0);
        uint32_t bb = st + (pass == 1 ? 3 * TILE_B : 2 * TILE_B);
#pragma unroll
        for (int ks = 0; ks < 2; ks++) {
            uint32_t kcol = (uint32_t)(ks * 16 + lk * 8) * 2;
            uint32_t A[2][4];
#pragma unroll
            for (int mf = 0; mf < 2; mf++) {
                uint32_t ad = ab + (uint32_t)(warp_m * 32 + mf * 16 + lsel * 8 + lrow) * 80 + kcol;
                ldsm4(A[mf], ad);
            }
            uint32_t Bv[2][4];
#pragma unroll
            for (int nb = 0; nb < 2; nb++) {
                uint32_t bd = bb + (uint32_t)(warp_n * 32 + nb * 16 + lsel * 8 + lrow) * 80 + kcol;
                ldsm4(Bv[nb], bd);   // r0=b0(2nb) r1=b0(2nb+1) r2=b1(2nb) r3=b1(2nb+1)
            }
#pragma unroll
            for (int nb = 0; nb < 2; nb++) {
#pragma unroll
                for (int mf = 0; mf < 2; mf++) {
                    mma16816(acc[mf][2 * nb],     A[mf], Bv[nb][0], Bv[nb][2]);
                    mma16816(acc[mf][2 * nb + 1], A[mf], Bv[nb][1], Bv[nb][3]);
                }
            }
        }
    }
}

// stage loader for 512 threads: 2048 x 16B per chunk, 4 per thread
#define LOADC(c) do { \
    uint32_t st_ = sb + (uint32_t)(((c) & (NSTAGE - 1)) * STAGE_B); \
    int kof_ = (c) * 32; \
    _Pragma("unroll") \
    for (int j_ = 0; j_ < 4; j_++) { \
        int i_ = tid + 512 * j_; \
        int tile_ = i_ >> 9; int row_ = (i_ >> 2) & 127; int seg_ = i_ & 3; \
        uint32_t dst_ = st_ + (uint32_t)(tile_ * TILE_B + row_ * 80 + seg_ * 16); \
        const __nv_bfloat16* src_ = sPtr[tile_][row_] + kof_ + seg_ * 8; \
        CP16(dst_, src_); \
    } \
    CP_COMMIT(); } while (0)

// multistage mainloop: 1 sync per chunk.
// order: wait(chunk c ready) -> sync (publish + license overwrite of stage
// computed at c-1) -> issue load(c+3) -> compute(c)
#define MAINLOOP(NC) do { \
    LOADC(0); LOADC(1); LOADC(2); \
    for (int c = 0; c < (NC); c++) { \
        if (c + 2 < (NC)) CP_WAITN(2); \
        else if (c + 1 < (NC)) CP_WAITN(1); \
        else CP_WAITN(0); \
        __syncthreads(); \
        if (c + 3 < (NC)) LOADC(c + 3); \
        compute_chunk(sb + (uint32_t)((c & (NSTAGE - 1)) * STAGE_B), warp_m, warp_n, lane, acc); \
    } } while (0)

// ---------------- init / router ----------------
__global__ void k_init() { if (threadIdx.x < NE) g_counts[threadIdx.x] = 0; }

__global__ void k_router(const float* __restrict__ x, const float* __restrict__ gW,
                         const float* __restrict__ gb) {
    int t = (blockIdx.x * blockDim.x + threadIdx.x) >> 5;
    int lane = threadIdx.x & 31;
    if (t >= TTOK) return;
    const float* xr = x + (size_t)t * DM;
    float acc[NE];
#pragma unroll
    for (int e = 0; e < NE; e++) acc[e] = 0.f;
    for (int i = lane; i < DM; i += 32) {
        float xv = xr[i];
#pragma unroll
        for (int e = 0; e < NE; e++) acc[e] += xv * gW[e * DM + i];
    }
#pragma unroll
    for (int e = 0; e < NE; e++)
#pragma unroll
        for (int o = 16; o > 0; o >>= 1) acc[e] += __shfl_down_sync(0xffffffffu, acc[e], o);
    if (lane == 0) {
        float best = -1e30f, sec = -1e30f; int b0 = 0, b1 = 0;
#pragma unroll
        for (int e = 0; e < NE; e++) {
            float l = acc[e] + gb[e];
            if (l > best) { sec = best; b1 = b0; best = l; b0 = e; }
            else if (l > sec) { sec = l; b1 = e; }
        }
        float ex = expf(sec - best);
        float inv = 1.f / (1.f + ex);
        int i0 = atomicAdd(&g_counts[b0], 1);
        g_pair[b0][i0] = t * 2;     g_wt[b0][i0] = inv;
        int i1 = atomicAdd(&g_counts[b1], 1);
        g_pair[b1][i1] = t * 2 + 1; g_wt[b1][i1] = ex * inv;
    }
}

// ---------------- fp32 -> bf16 hi/lo split ----------------
__device__ __forceinline__ void split_store(const float4* in, __nv_bfloat16* hi,
                                            __nv_bfloat16* lo, size_t i) {
    float4 v = in[i];
    __nv_bfloat16 h0 = __float2bfloat16(v.x), h1 = __float2bfloat16(v.y);
    __nv_bfloat16 h2 = __float2bfloat16(v.z), h3 = __float2bfloat16(v.w);
    __nv_bfloat162* H = (__nv_bfloat162*)hi;
    __nv_bfloat162* L = (__nv_bfloat162*)lo;
    H[2 * i]     = __nv_bfloat162(h0, h1);
    H[2 * i + 1] = __nv_bfloat162(h2, h3);
    L[2 * i]     = __nv_bfloat162(__float2bfloat16(v.x - __bfloat162float(h0)),
                                  __float2bfloat16(v.y - __bfloat162float(h1)));
    L[2 * i + 1] = __nv_bfloat162(__float2bfloat16(v.z - __bfloat162float(h2)),
                                  __float2bfloat16(v.w - __bfloat162float(h3)));
}
__global__ void k_split_x(const float4* __restrict__ in, int n4) {
    int i = blockIdx.x * blockDim.x + threadIdx.x;
    if (i < n4) split_store(in, g_xh, g_xl, i);
}
__global__ void k_split_w(const float4* __restrict__ Wg, const float4* __restrict__ W1,
                          const float4* __restrict__ W2, int n4) {
    int i = blockIdx.x * blockDim.x + threadIdx.x;
    if (i >= n4) return;
    switch (blockIdx.y) {
        case 0: split_store(Wg, g_Wgh, g_Wgl, i); break;
        case 1: split_store(W1, g_W1h, g_W1l, i); break;
        default: split_store(W2, g_W2h, g_W2l, i); break;
    }
}

// ---------------- GEMM1: C=[G|V] = X @ [Wg_n|W1_n]^T, SwiGLU epilogue ----------------
// grid (DFF/64, TTOK/BM, NE). 512 threads, warps 4x4, warp tile 32m x 32n.
#define NC1 (DM / 32)   // 32
__global__ __launch_bounds__(512, 1)
void k_mma1() {
    int e = blockIdx.z;
    int cnt = g_counts[e];
    int m0 = blockIdx.y * BM;
    if (m0 >= cnt) return;
    int n0 = blockIdx.x * 64;

    extern __shared__ char dsm[];
    __shared__ int sPair[BM];
    __shared__ const __nv_bfloat16* sPtr[4][BM];

    int tid = threadIdx.x, wid = tid >> 5, lane = tid & 31;
    int warp_m = wid & 3, warp_n = wid >> 2;
    int group = lane >> 2, tq = lane & 3;
    uint32_t sb = smem_u32(dsm);

    if (tid < BM) {
        int r = m0 + tid;
        int p = g_pair[e][r < cnt ? r : cnt - 1];
        sPair[tid] = p;
        size_t tok = (size_t)(p >> 1) * DM;
        sPtr[0][tid] = g_xh + tok;
        sPtr[1][tid] = g_xl + tok;
        size_t eo = (size_t)e * DFF * DM;
        sPtr[2][tid] = (tid < 64) ? g_Wgh + eo + (size_t)(n0 + tid) * DM
                                  : g_W1h + eo + (size_t)(n0 + tid - 64) * DM;
        sPtr[3][tid] = (tid < 64) ? g_Wgl + eo + (size_t)(n0 + tid) * DM
                                  : g_W1l + eo + (size_t)(n0 + tid - 64) * DM;
    }
    __syncthreads();

    float acc[2][4][4];
#pragma unroll
    for (int a = 0; a < 2; a++)
#pragma unroll
        for (int b = 0; b < 4; b++)
#pragma unroll
            for (int c = 0; c < 4; c++) acc[a][b][c] = 0.f;

    MAINLOOP(NC1);
    __syncthreads();

    // stage C through smem (reuse pipeline buffers), combine G/V -> H hi/lo
    float* sC = (float*)dsm;  // [128][132]
#pragma unroll
    for (int mf = 0; mf < 2; mf++)
#pragma unroll
        for (int nf = 0; nf < 4; nf++) {
            int r = warp_m * 32 + mf * 16 + group;
            int col = warp_n * 32 + nf * 8 + tq * 2;
            *(float2*)&sC[r * 132 + col]       = make_float2(acc[mf][nf][0], acc[mf][nf][1]);
            *(float2*)&sC[(r + 8) * 132 + col] = make_float2(acc[mf][nf][2], acc[mf][nf][3]);
        }
    __syncthreads();

    int row = tid >> 2, q = tid & 3;   // 4 threads/row, 16 cols each
    if (m0 + row < cnt) {
        int pair = sPair[row];
        const float* cg = sC + row * 132 + q * 16;
        const float* cv = cg + 64;
        uint32_t hh[8], hl[8];
#pragma unroll
        for (int j = 0; j < 8; j++) {
            float g0 = cg[2 * j], g1 = cg[2 * j + 1];
            float v0 = cv[2 * j], v1 = cv[2 * j + 1];
            float h0 = g0 / (1.f + __expf(-g0)) * v0;
            float h1 = g1 / (1.f + __expf(-g1)) * v1;
            __nv_bfloat16 b0 = __float2bfloat16(h0), b1 = __float2bfloat16(h1);
            __nv_bfloat162 hi2(b0, b1);
            __nv_bfloat162 lo2(__float2bfloat16(h0 - __bfloat162float(b0)),
                               __float2bfloat16(h1 - __bfloat162float(b1)));
            hh[j] = *(uint32_t*)&hi2;
            hl[j] = *(uint32_t*)&lo2;
        }
        uint4* dh = (uint4*)(g_Hh + (size_t)pair * DFF + n0 + q * 16);
        uint4* dl = (uint4*)(g_Hl + (size_t)pair * DFF + n0 + q * 16);
        dh[0] = ((uint4*)hh)[0]; dh[1] = ((uint4*)hh)[1];
        dl[0] = ((uint4*)hl)[0]; dl[1] = ((uint4*)hl)[1];
    }
}

// ---------------- GEMM2: Y = (H @ W2^T) * w ----------------
// grid (DM/128, TTOK/BM, NE). 512 threads, warps 4x4, warp tile 32m x 32n.
#define NC2 (DFF / 32)  // 128
__global__ __launch_bounds__(512, 1)
void k_mma2() {
    int e = blockIdx.z;
    int cnt = g_counts[e];
    int m0 = blockIdx.y * BM;
    if (m0 >= cnt) return;
    int n0 = blockIdx.x * 128;

    extern __shared__ char dsm[];
    __shared__ int sPair[BM];
    __shared__ float sWt[BM];
    __shared__ const __nv_bfloat16* sPtr[4][BM];

    int tid = threadIdx.x, wid = tid >> 5, lane = tid & 31;
    int warp_m = wid & 3, warp_n = wid >> 2;
    int group = lane >> 2, tq = lane & 3;
    uint32_t sb = smem_u32(dsm);

    if (tid < BM) {
        int r = m0 + tid;
        int rr = r < cnt ? r : cnt - 1;
        int p = g_pair[e][rr];
        sPair[tid] = p;
        sWt[tid] = g_wt[e][rr];
        size_t po = (size_t)p * DFF;
        sPtr[0][tid] = g_Hh + po;
        sPtr[1][tid] = g_Hl + po;
        size_t eo = (size_t)e * DM * DFF;
        sPtr[2][tid] = g_W2h + eo + (size_t)(n0 + tid) * DFF;
        sPtr[3][tid] = g_W2l + eo + (size_t)(n0 + tid) * DFF;
    }
    __syncthreads();

    float acc[2][4][4];
#pragma unroll
    for (int a = 0; a < 2; a++)
#pragma unroll
        for (int b = 0; b < 4; b++)
#pragma unroll
            for (int c = 0; c < 4; c++) acc[a][b][c] = 0.f;

    MAINLOOP(NC2);

    // epilogue: scale by combine weight, write per-pair rows
#pragma unroll
    for (int mf = 0; mf < 2; mf++)
#pragma unroll
        for (int sub = 0; sub < 2; sub++) {
            int r = warp_m * 32 + mf * 16 + group + sub * 8;
            if (m0 + r < cnt) {
                float w = sWt[r];
                float* Y = g_Y + (size_t)sPair[r] * DM + n0;
#pragma unroll
                for (int nf = 0; nf < 4; nf++) {
                    int col = warp_n * 32 + nf * 8 + tq * 2;
                    float2 v = make_float2(acc[mf][nf][sub * 2] * w,
                                           acc[mf][nf][sub * 2 + 1] * w);
                    *(float2*)(Y + col) = v;
                }
            }
        }
}

// ---------------- combine ----------------
__global__ void k_combine(float* __restrict__ out) {
    size_t i = (size_t)blockIdx.x * blockDim.x + threadIdx.x;
    const float4* y = (const float4*)g_Y;
    int t = (int)(i >> 8);
    int j = (int)(i & 255);
    float4 a = y[(size_t)(2 * t) * 256 + j];
    float4 b = y[(size_t)(2 * t + 1) * 256 + j];
    float4 o;
    o.x = a.x + b.x; o.y = a.y + b.y; o.z = a.z + b.z; o.w = a.w + b.w;
    ((float4*)out)[i] = o;
}

// ---------------- launch ----------------
extern "C" void kernel_launch(void* const* d_in, const int* in_sizes, int n_in,
                              void* d_out, int out_size) {
    const float* x  = (const float*)d_in[0];
    const float* gW = (const float*)d_in[1];
    const float* gb = (const float*)d_in[2];
    const float* Wg = (const float*)d_in[3];
    const float* W1 = (const float*)d_in[4];
    const float* W2 = (const float*)d_in[5];
    float* out = (float*)d_out;

    cudaFuncSetAttribute(k_mma1, cudaFuncAttributeMaxDynamicSharedMemorySize, SMEM_DYN);
    cudaFuncSetAttribute(k_mma2, cudaFuncAttributeMaxDynamicSharedMemorySize, SMEM_DYN);

    k_init<<<1, 32>>>();
    k_router<<<TTOK / 8, 256>>>(x, gW, gb);

    int n4x = TTOK * DM / 4;
    k_split_x<<<(n4x + 255) / 256, 256>>>((const float4*)x, n4x);
    int n4w = NE * DFF * DM / 4;
    dim3 gs((n4w + 255) / 256, 3);
    k_split_w<<<gs, 256>>>((const float4*)Wg, (const float4*)W1, (const float4*)W2, n4w);

    dim3 g1(DFF / 64, TTOK / BM, NE);   // 64 x 64 x 8
    k_mma1<<<g1, 512, SMEM_DYN>>>();

    dim3 g2(DM / 128, TTOK / BM, NE);   // 8 x 64 x 8
    k_mma2<<<g2, 512, SMEM_DYN>>>();

    k_combine<<<(TTOK * (DM / 4)) / 256, 256>>>(out);
}

// round 17
// speedup vs baseline: 1.3773x; 1.3773x over previous
#include <cuda_runtime.h>
#include <cuda_bf16.h>
#include <cstdint>
#include <math.h>

#define TTOK 8192
#define DM   1024
#define DFF  4096
#define NE   8
#define BM   128

// smem tile geometry: 128 rows x 32 bf16 (64B data), row stride 80B (20 words
// -> conflict-free ldmatrix row gathers). 4 tiles/stage (Ah,Al,Bh,Bl), 2 stages.
#define TILE_B   10240       // 128 * 80
#define STAGE_B  40960       // 4 * TILE_B
#define SMEM_DYN (2 * STAGE_B)

// ---------------- device scratch ----------------
__device__ int   g_counts[NE];
__device__ int   g_pair[NE][TTOK];
__device__ float g_wt[NE][TTOK];
__device__ __nv_bfloat16 g_xh[(size_t)TTOK * DM],        g_xl[(size_t)TTOK * DM];
__device__ __nv_bfloat16 g_Wgh[(size_t)NE * DFF * DM],   g_Wgl[(size_t)NE * DFF * DM];
__device__ __nv_bfloat16 g_W1h[(size_t)NE * DFF * DM],   g_W1l[(size_t)NE * DFF * DM];
__device__ __nv_bfloat16 g_W2h[(size_t)NE * DM * DFF],   g_W2l[(size_t)NE * DM * DFF];
__device__ __nv_bfloat16 g_Hh[(size_t)2 * TTOK * DFF],   g_Hl[(size_t)2 * TTOK * DFF];
__device__ float g_Y[(size_t)2 * TTOK * DM];

// ---------------- helpers ----------------
__device__ __forceinline__ uint32_t smem_u32(const void* p) {
    uint32_t a;
    asm("{ .reg .u64 t; cvta.to.shared.u64 t, %1; cvt.u32.u64 %0, t; }" : "=r"(a) : "l"(p));
    return a;
}
__device__ __forceinline__ void ldsm4(uint32_t* r, uint32_t addr) {
    asm volatile("ldmatrix.sync.aligned.m8n8.x4.shared.b16 {%0,%1,%2,%3}, [%4];"
                 : "=r"(r[0]), "=r"(r[1]), "=r"(r[2]), "=r"(r[3]) : "r"(addr));
}
__device__ __forceinline__ void mma16816(float* d, const uint32_t* A, uint32_t b0, uint32_t b1) {
    asm volatile(
        "mma.sync.aligned.m16n8k16.row.col.f32.bf16.bf16.f32 "
        "{%0,%1,%2,%3}, {%4,%5,%6,%7}, {%8,%9}, {%0,%1,%2,%3};"
        : "+f"(d[0]), "+f"(d[1]), "+f"(d[2]), "+f"(d[3])
        : "r"(A[0]), "r"(A[1]), "r"(A[2]), "r"(A[3]), "r"(b0), "r"(b1));
}
#define CP16(dst, src) asm volatile("cp.async.cg.shared.global [%0], [%1], 16;" :: "r"(dst), "l"(src) : "memory")
#define CP_COMMIT()    asm volatile("cp.async.commit_group;" ::: "memory")
#define CP_WAIT1()     asm volatile("cp.async.wait_group 1;" ::: "memory")
#define CP_WAIT0()     asm volatile("cp.async.wait_group 0;" ::: "memory")

// 3-pass hi/lo compute on one K-chunk (32 bf16) with HOISTED fragment loads:
// each fragment is read from smem ONCE per k-slice and reused for all passes
// (Ah*Bh, Ah*Bl, Al*Bh issued from registers). Cuts LDSM traffic 1.5x.
// Tiles at st+0:Ah, +TILE_B:Al, +2*TILE_B:Bh, +3*TILE_B:Bl. Warp tile 32m x 64n.
__device__ __forceinline__ void compute_chunk(uint32_t st, int warp_m, int warp_n,
                                              int lane, float acc[2][8][4]) {
    int lrow = lane & 7;
    int lsel = (lane >> 3) & 1;
    int lk   = lane >> 4;
#pragma unroll
    for (int ks = 0; ks < 2; ks++) {
        uint32_t kcol = (uint32_t)(ks * 16 + lk * 8) * 2;
        uint32_t Ah[2][4], Al[2][4];
#pragma unroll
        for (int mf = 0; mf < 2; mf++) {
            uint32_t rof = (uint32_t)(warp_m * 32 + mf * 16 + lsel * 8 + lrow) * 80 + kcol;
            ldsm4(Ah[mf], st + rof);
            ldsm4(Al[mf], st + TILE_B + rof);
        }
        // process B in two nb-halves to cap live registers
#pragma unroll
        for (int half = 0; half < 2; half++) {
            uint32_t Bh[2][4], Bl[2][4];
#pragma unroll
            for (int nb = 0; nb < 2; nb++) {
                uint32_t rof = (uint32_t)(warp_n * 64 + (half * 2 + nb) * 16 + lsel * 8 + lrow) * 80 + kcol;
                ldsm4(Bh[nb], st + 2 * TILE_B + rof);
                ldsm4(Bl[nb], st + 3 * TILE_B + rof);
            }
#pragma unroll
            for (int nb = 0; nb < 2; nb++) {
                int nf = (half * 2 + nb) * 2;
#pragma unroll
                for (int mf = 0; mf < 2; mf++) {
                    mma16816(acc[mf][nf],     Ah[mf], Bh[nb][0], Bh[nb][2]);
                    mma16816(acc[mf][nf + 1], Ah[mf], Bh[nb][1], Bh[nb][3]);
                    mma16816(acc[mf][nf],     Ah[mf], Bl[nb][0], Bl[nb][2]);
                    mma16816(acc[mf][nf + 1], Ah[mf], Bl[nb][1], Bl[nb][3]);
                    mma16816(acc[mf][nf],     Al[mf], Bh[nb][0], Bh[nb][2]);
                    mma16816(acc[mf][nf + 1], Al[mf], Bh[nb][1], Bh[nb][3]);
                }
            }
        }
    }
}

// stage loader: sPtr[tile][row] -> row base pointer; k-chunk c
#define LOADC(c) do { \
    uint32_t st_ = sb + (uint32_t)(((c) & 1) * STAGE_B); \
    int kof_ = (c) * 32; \
    _Pragma("unroll") \
    for (int j_ = 0; j_ < 8; j_++) { \
        int i_ = tid + 256 * j_; \
        int tile_ = i_ >> 9; int row_ = (i_ >> 2) & 127; int seg_ = i_ & 3; \
        uint32_t dst_ = st_ + (uint32_t)(tile_ * TILE_B + row_ * 80 + seg_ * 16); \
        const __nv_bfloat16* src_ = sPtr[tile_][row_] + kof_ + seg_ * 8; \
        CP16(dst_, src_); \
    } \
    CP_COMMIT(); } while (0)

// ---------------- init / router ----------------
__global__ void k_init() { if (threadIdx.x < NE) g_counts[threadIdx.x] = 0; }

__global__ void k_router(const float* __restrict__ x, const float* __restrict__ gW,
                         const float* __restrict__ gb) {
    int t = (blockIdx.x * blockDim.x + threadIdx.x) >> 5;
    int lane = threadIdx.x & 31;
    if (t >= TTOK) return;
    const float* xr = x + (size_t)t * DM;
    float acc[NE];
#pragma unroll
    for (int e = 0; e < NE; e++) acc[e] = 0.f;
    for (int i = lane; i < DM; i += 32) {
        float xv = xr[i];
#pragma unroll
        for (int e = 0; e < NE; e++) acc[e] += xv * gW[e * DM + i];
    }
#pragma unroll
    for (int e = 0; e < NE; e++)
#pragma unroll
        for (int o = 16; o > 0; o >>= 1) acc[e] += __shfl_down_sync(0xffffffffu, acc[e], o);
    if (lane == 0) {
        float best = -1e30f, sec = -1e30f; int b0 = 0, b1 = 0;
#pragma unroll
        for (int e = 0; e < NE; e++) {
            float l = acc[e] + gb[e];
            if (l > best) { sec = best; b1 = b0; best = l; b0 = e; }
            else if (l > sec) { sec = l; b1 = e; }
        }
        float ex = expf(sec - best);
        float inv = 1.f / (1.f + ex);
        int i0 = atomicAdd(&g_counts[b0], 1);
        g_pair[b0][i0] = t * 2;     g_wt[b0][i0] = inv;
        int i1 = atomicAdd(&g_counts[b1], 1);
        g_pair[b1][i1] = t * 2 + 1; g_wt[b1][i1] = ex * inv;
    }
}

// ---------------- fp32 -> bf16 hi/lo split ----------------
__device__ __forceinline__ void split_store(const float4* in, __nv_bfloat16* hi,
                                            __nv_bfloat16* lo, size_t i) {
    float4 v = in[i];
    __nv_bfloat16 h0 = __float2bfloat16(v.x), h1 = __float2bfloat16(v.y);
    __nv_bfloat16 h2 = __float2bfloat16(v.z), h3 = __float2bfloat16(v.w);
    __nv_bfloat162* H = (__nv_bfloat162*)hi;
    __nv_bfloat162* L = (__nv_bfloat162*)lo;
    H[2 * i]     = __nv_bfloat162(h0, h1);
    H[2 * i + 1] = __nv_bfloat162(h2, h3);
    L[2 * i]     = __nv_bfloat162(__float2bfloat16(v.x - __bfloat162float(h0)),
                                  __float2bfloat16(v.y - __bfloat162float(h1)));
    L[2 * i + 1] = __nv_bfloat162(__float2bfloat16(v.z - __bfloat162float(h2)),
                                  __float2bfloat16(v.w - __bfloat162float(h3)));
}
__global__ void k_split_x(const float4* __restrict__ in, int n4) {
    int i = blockIdx.x * blockDim.x + threadIdx.x;
    if (i < n4) split_store(in, g_xh, g_xl, i);
}
__global__ void k_split_w(const float4* __restrict__ Wg, const float4* __restrict__ W1,
                          const float4* __restrict__ W2, int n4) {
    int i = blockIdx.x * blockDim.x + threadIdx.x;
    if (i >= n4) return;
    switch (blockIdx.y) {
        case 0: split_store(Wg, g_Wgh, g_Wgl, i); break;
        case 1: split_store(W1, g_W1h, g_W1l, i); break;
        default: split_store(W2, g_W2h, g_W2l, i); break;
    }
}

// ---------------- GEMM1: C=[G|V] = X @ [Wg_n|W1_n]^T, SwiGLU epilogue ----------------
// grid (DFF/64, TTOK/BM, NE). n0 covers 64 output cols of both G and V.
#define NC1 (DM / 32)   // 32
__global__ __launch_bounds__(256, 2)
void k_mma1() {
    int e = blockIdx.z;
    int cnt = g_counts[e];
    int m0 = blockIdx.y * BM;
    if (m0 >= cnt) return;
    int n0 = blockIdx.x * 64;

    extern __shared__ char dsm[];
    __shared__ int sPair[BM];
    __shared__ const __nv_bfloat16* sPtr[4][BM];

    int tid = threadIdx.x, wid = tid >> 5, lane = tid & 31;
    int warp_m = wid & 3, warp_n = wid >> 2;
    int group = lane >> 2, tq = lane & 3;
    uint32_t sb = smem_u32(dsm);

    if (tid < BM) {
        int r = m0 + tid;
        int p = g_pair[e][r < cnt ? r : cnt - 1];
        sPair[tid] = p;
        size_t tok = (size_t)(p >> 1) * DM;
        sPtr[0][tid] = g_xh + tok;
        sPtr[1][tid] = g_xl + tok;
        size_t eo = (size_t)e * DFF * DM;
        sPtr[2][tid] = (tid < 64) ? g_Wgh + eo + (size_t)(n0 + tid) * DM
                                  : g_W1h + eo + (size_t)(n0 + tid - 64) * DM;
        sPtr[3][tid] = (tid < 64) ? g_Wgl + eo + (size_t)(n0 + tid) * DM
                                  : g_W1l + eo + (size_t)(n0 + tid - 64) * DM;
    }
    __syncthreads();

    float acc[2][8][4];
#pragma unroll
    for (int a = 0; a < 2; a++)
#pragma unroll
        for (int b = 0; b < 8; b++)
#pragma unroll
            for (int c = 0; c < 4; c++) acc[a][b][c] = 0.f;

    LOADC(0); LOADC(1);
    for (int c = 0; c < NC1; c++) {
        if (c < NC1 - 1) CP_WAIT1(); else CP_WAIT0();
        __syncthreads();
        compute_chunk(sb + (uint32_t)((c & 1) * STAGE_B), warp_m, warp_n, lane, acc);
        __syncthreads();
        if (c + 2 < NC1) LOADC(c + 2);
    }

    // stage C through smem (reuse pipeline buffers), combine G/V -> H hi/lo
    float* sC = (float*)dsm;  // [128][132]
#pragma unroll
    for (int mf = 0; mf < 2; mf++)
#pragma unroll
        for (int nf = 0; nf < 8; nf++) {
            int r = warp_m * 32 + mf * 16 + group;
            int col = warp_n * 64 + nf * 8 + tq * 2;
            *(float2*)&sC[r * 132 + col]       = make_float2(acc[mf][nf][0], acc[mf][nf][1]);
            *(float2*)&sC[(r + 8) * 132 + col] = make_float2(acc[mf][nf][2], acc[mf][nf][3]);
        }
    __syncthreads();

    int row = tid >> 1, half = tid & 1;
    if (m0 + row < cnt) {
        int pair = sPair[row];
        const float* cg = sC + row * 132 + half * 32;
        const float* cv = cg + 64;
        uint32_t hh[16], hl[16];
#pragma unroll
        for (int j = 0; j < 16; j++) {
            float g0 = cg[2 * j], g1 = cg[2 * j + 1];
            float v0 = cv[2 * j], v1 = cv[2 * j + 1];
            float h0 = g0 / (1.f + __expf(-g0)) * v0;
            float h1 = g1 / (1.f + __expf(-g1)) * v1;
            __nv_bfloat16 b0 = __float2bfloat16(h0), b1 = __float2bfloat16(h1);
            __nv_bfloat162 hi2(b0, b1);
            __nv_bfloat162 lo2(__float2bfloat16(h0 - __bfloat162float(b0)),
                               __float2bfloat16(h1 - __bfloat162float(b1)));
            hh[j] = *(uint32_t*)&hi2;
            hl[j] = *(uint32_t*)&lo2;
        }
        uint4* dh = (uint4*)(g_Hh + (size_t)pair * DFF + n0 + half * 32);
        uint4* dl = (uint4*)(g_Hl + (size_t)pair * DFF + n0 + half * 32);
#pragma unroll
        for (int q = 0; q < 4; q++) { dh[q] = ((uint4*)hh)[q]; dl[q] = ((uint4*)hl)[q]; }
    }
}

// ---------------- GEMM2: Y = (H @ W2^T) * w ----------------
// grid (DM/128, TTOK/BM, NE)
#define NC2 (DFF / 32)  // 128
__global__ __launch_bounds__(256, 2)
void k_mma2() {
    int e = blockIdx.z;
    int cnt = g_counts[e];
    int m0 = blockIdx.y * BM;
    if (m0 >= cnt) return;
    int n0 = blockIdx.x * 128;

    extern __shared__ char dsm[];
    __shared__ int sPair[BM];
    __shared__ float sWt[BM];
    __shared__ const __nv_bfloat16* sPtr[4][BM];

    int tid = threadIdx.x, wid = tid >> 5, lane = tid & 31;
    int warp_m = wid & 3, warp_n = wid >> 2;
    int group = lane >> 2, tq = lane & 3;
    uint32_t sb = smem_u32(dsm);

    if (tid < BM) {
        int r = m0 + tid;
        int rr = r < cnt ? r : cnt - 1;
        int p = g_pair[e][rr];
        sPair[tid] = p;
        sWt[tid] = g_wt[e][rr];
        size_t po = (size_t)p * DFF;
        sPtr[0][tid] = g_Hh + po;
        sPtr[1][tid] = g_Hl + po;
        size_t eo = (size_t)e * DM * DFF;
        sPtr[2][tid] = g_W2h + eo + (size_t)(n0 + tid) * DFF;
        sPtr[3][tid] = g_W2l + eo + (size_t)(n0 + tid) * DFF;
    }
    __syncthreads();

    float acc[2][8][4];
#pragma unroll
    for (int a = 0; a < 2; a++)
#pragma unroll
        for (int b = 0; b < 8; b++)
#pragma unroll
            for (int c = 0; c < 4; c++) acc[a][b][c] = 0.f;

    LOADC(0); LOADC(1);
    for (int c = 0; c < NC2; c++) {
        if (c < NC2 - 1) CP_WAIT1(); else CP_WAIT0();
        __syncthreads();
        compute_chunk(sb + (uint32_t)((c & 1) * STAGE_B), warp_m, warp_n, lane, acc);
        __syncthreads();
        if (c + 2 < NC2) LOADC(c + 2);
    }

    // epilogue: scale by combine weight, write per-pair rows
#pragma unroll
    for (int mf = 0; mf < 2; mf++)
#pragma unroll
        for (int sub = 0; sub < 2; sub++) {
            int r = warp_m * 32 + mf * 16 + group + sub * 8;
            if (m0 + r < cnt) {
                float w = sWt[r];
                float* Y = g_Y + (size_t)sPair[r] * DM + n0;
#pragma unroll
                for (int nf = 0; nf < 8; nf++) {
                    int col = warp_n * 64 + nf * 8 + tq * 2;
                    float2 v = make_float2(acc[mf][nf][sub * 2] * w,
                                           acc[mf][nf][sub * 2 + 1] * w);
                    *(float2*)(Y + col) = v;
                }
            }
        }
}

// ---------------- combine ----------------
__global__ void k_combine(float* __restrict__ out) {
    size_t i = (size_t)blockIdx.x * blockDim.x + threadIdx.x;
    const float4* y = (const float4*)g_Y;
    int t = (int)(i >> 8);
    int j = (int)(i & 255);
    float4 a = y[(size_t)(2 * t) * 256 + j];
    float4 b = y[(size_t)(2 * t + 1) * 256 + j];
    float4 o;
    o.x = a.x + b.x; o.y = a.y + b.y; o.z = a.z + b.z; o.w = a.w + b.w;
    ((float4*)out)[i] = o;
}

// ---------------- launch ----------------
extern "C" void kernel_launch(void* const* d_in, const int* in_sizes, int n_in,
                              void* d_out, int out_size) {
    const float* x  = (const float*)d_in[0];
    const float* gW = (const float*)d_in[1];
    const float* gb = (const float*)d_in[2];
    const float* Wg = (const float*)d_in[3];
    const float* W1 = (const float*)d_in[4];
    const float* W2 = (const float*)d_in[5];
    float* out = (float*)d_out;

    cudaFuncSetAttribute(k_mma1, cudaFuncAttributeMaxDynamicSharedMemorySize, SMEM_DYN);
    cudaFuncSetAttribute(k_mma2, cudaFuncAttributeMaxDynamicSharedMemorySize, SMEM_DYN);

    k_init<<<1, 32>>>();
    k_router<<<TTOK / 8, 256>>>(x, gW, gb);

    int n4x = TTOK * DM / 4;
    k_split_x<<<(n4x + 255) / 256, 256>>>((const float4*)x, n4x);
    int n4w = NE * DFF * DM / 4;
    dim3 gs((n4w + 255) / 256, 3);
    k_split_w<<<gs, 256>>>((const float4*)Wg, (const float4*)W1, (const float4*)W2, n4w);

    dim3 g1(DFF / 64, TTOK / BM, NE);   // 64 x 64 x 8
    k_mma1<<<g1, 256, SMEM_DYN>>>();

    dim3 g2(DM / 128, TTOK / BM, NE);   // 8 x 64 x 8
    k_mma2<<<g2, 256, SMEM_DYN>>>();

    k_combine<<<(TTOK * (DM / 4)) / 256, 256>>>(out);
}